// round 2
// baseline (speedup 1.0000x reference)
#include <cuda_runtime.h>
#include <math.h>

#define F_DIM   128
#define NRBF    20
#define CUTOFF  5.0f
#define N_PAD   50048   // 391 * 128
#define PI_F    3.14159265358979323846f

// Scratch (allocation-free rule: __device__ globals)
__device__ float g_h[(size_t)N_PAD * 128];
__device__ float g_phi[(size_t)N_PAD * 384];

// ---------------------------------------------------------------------------
// GEMM: C[M x N] = act(A[M x 128] @ W[128 x N] + bias), K fixed = 128.
// BM=BN=128, BK=32, 256 threads, 8x8 micro-tile.
// Rows >= Mload are zero-filled on load; stores cover full 128-row block
// (C buffers are padded to N_PAD rows).
// ---------------------------------------------------------------------------
__global__ __launch_bounds__(256) void gemm_bias_act(
    const float* __restrict__ A, const float* __restrict__ W,
    const float* __restrict__ bias, float* __restrict__ C,
    int Mload, int N, int applySilu)
{
    __shared__ float As[128][33];   // [m][k], padded
    __shared__ float Ws[32][128];   // [k][n]

    const int tid = threadIdx.x;
    const int tx = tid % 16;        // col group
    const int ty = tid / 16;        // row group
    const int row0 = blockIdx.x * 128;
    const int col0 = blockIdx.y * 128;

    float acc[8][8];
#pragma unroll
    for (int i = 0; i < 8; i++)
#pragma unroll
        for (int j = 0; j < 8; j++) acc[i][j] = 0.0f;

    for (int k0 = 0; k0 < 128; k0 += 32) {
        // Load A tile (128 x 32), zero-fill out-of-range rows.
#pragma unroll
        for (int it = 0; it < 4; it++) {
            int r  = (tid / 8) + it * 32;     // 0..127
            int kq = (tid % 8) * 4;           // 0,4,...,28
            float4 v = make_float4(0.f, 0.f, 0.f, 0.f);
            int grow = row0 + r;
            if (grow < Mload)
                v = *(const float4*)(A + (size_t)grow * 128 + k0 + kq);
            As[r][kq + 0] = v.x; As[r][kq + 1] = v.y;
            As[r][kq + 2] = v.z; As[r][kq + 3] = v.w;
        }
        // Load W tile (32 x 128)
        {
            const float* wbase = W + (size_t)k0 * N + col0;
#pragma unroll
            for (int it = 0; it < 4; it++) {
                int kr = (tid / 32) + it * 8;     // 0..31
                int cq = (tid % 32) * 4;          // 0..124
                float4 v = *(const float4*)(wbase + (size_t)kr * N + cq);
                *(float4*)&Ws[kr][cq] = v;
            }
        }
        __syncthreads();

#pragma unroll
        for (int k = 0; k < 32; k++) {
            float a[8], w[8];
#pragma unroll
            for (int i = 0; i < 8; i++) a[i] = As[ty * 8 + i][k];
            float4 w0 = *(float4*)&Ws[k][tx * 8];
            float4 w1 = *(float4*)&Ws[k][tx * 8 + 4];
            w[0] = w0.x; w[1] = w0.y; w[2] = w0.z; w[3] = w0.w;
            w[4] = w1.x; w[5] = w1.y; w[6] = w1.z; w[7] = w1.w;
#pragma unroll
            for (int i = 0; i < 8; i++)
#pragma unroll
                for (int j = 0; j < 8; j++)
                    acc[i][j] = fmaf(a[i], w[j], acc[i][j]);
        }
        __syncthreads();
    }

    // Epilogue: bias + optional silu, store (rows always in-range of padded C)
    float bcol[8];
#pragma unroll
    for (int j = 0; j < 8; j++) bcol[j] = bias[col0 + tx * 8 + j];

#pragma unroll
    for (int i = 0; i < 8; i++) {
        int grow = row0 + ty * 8 + i;
        float out[8];
#pragma unroll
        for (int j = 0; j < 8; j++) {
            float x = acc[i][j] + bcol[j];
            if (applySilu) x = x / (1.0f + __expf(-x));
            out[j] = x;
        }
        float* cp = C + (size_t)grow * N + col0 + tx * 8;
        *(float4*)cp       = make_float4(out[0], out[1], out[2], out[3]);
        *(float4*)(cp + 4) = make_float4(out[4], out[5], out[6], out[7]);
    }
}

// ---------------------------------------------------------------------------
// Edge kernel: 128 threads/block, thread f owns channels f, 128+f, 256+f.
// Wr columns held in registers (loop-invariant). sin(n*theta) by Chebyshev
// recurrence. node_vector gathered and messages scattered via shared staging
// so all LDG and atomics are fully coalesced.
// ---------------------------------------------------------------------------
__global__ __launch_bounds__(128, 4) void edge_kernel(
    const float* __restrict__ r_vec,
    const int2*  __restrict__ edge_idx,
    const float* __restrict__ node_vector,
    const float* __restrict__ Wr,
    const float* __restrict__ br,
    float* __restrict__ out_s,   // [N,128], pre-initialized with node_scalar
    float* __restrict__ out_v,   // [N,128,3], pre-initialized with node_vector
    int E)
{
    __shared__ float sm[384];
    const int f = threadIdx.x;

    float wr1[NRBF], wr2[NRBF], wr3[NRBF];
#pragma unroll
    for (int n = 0; n < NRBF; n++) {
        wr1[n] = Wr[n * 384 + f];
        wr2[n] = Wr[n * 384 + 128 + f];
        wr3[n] = Wr[n * 384 + 256 + f];
    }
    const float bias1 = br[f], bias2 = br[128 + f], bias3 = br[256 + f];

    for (int e = blockIdx.x; e < E; e += gridDim.x) {
        const int2 ei = __ldg(&edge_idx[e]);
        const int dst = ei.x;
        const int src = ei.y;
        const float rx = __ldg(&r_vec[3 * e]);
        const float ry = __ldg(&r_vec[3 * e + 1]);
        const float rz = __ldg(&r_vec[3 * e + 2]);

        // Stage node_vector[src] (coalesced)
        const float* nv = node_vector + (size_t)src * 384;
        sm[f]       = nv[f];
        sm[f + 128] = nv[f + 128];
        sm[f + 256] = nv[f + 256];

        const float d2   = rx * rx + ry * ry + rz * rz;
        const float d    = sqrtf(d2);
        const float invd = 1.0f / d;
        const float theta = d * (PI_F / CUTOFF);
        float s, c;
        __sincosf(theta, &s, &c);
        const float fcut = (d < CUTOFF) ? 0.5f * (c + 1.0f) : 0.0f;

        // rbf = sinc @ Wr + br  via trig recurrence:
        // sin((n+1)t) = 2cos(t)*sin(nt) - sin((n-1)t)
        float a1 = bias1, a2 = bias2, a3 = bias3;
        float sp = 0.0f, sc = s;
        const float twoC = 2.0f * c;
#pragma unroll
        for (int n = 0; n < NRBF; n++) {
            const float snc = sc * invd;
            a1 = fmaf(snc, wr1[n], a1);
            a2 = fmaf(snc, wr2[n], a2);
            a3 = fmaf(snc, wr3[n], a3);
            const float nx = fmaf(twoC, sc, -sp);
            sp = sc; sc = nx;
        }

        // Gather phi (coalesced)
        const float* ph = g_phi + (size_t)src * 384;
        const float pre1 = ph[f]       * a1 * fcut;
        const float pre2 = ph[f + 128] * a2 * fcut;
        const float pre3 = ph[f + 256] * a3 * fcut;

        __syncthreads();   // nv staged

        // Vector message (stride-3 shared reads: conflict-free, gcd(3,32)=1)
        const float v0 = sm[3 * f], v1 = sm[3 * f + 1], v2 = sm[3 * f + 2];
        const float hx = rx * invd, hy = ry * invd, hz = rz * invd;
        sm[3 * f]     = fmaf(v0, pre1, pre3 * hx);
        sm[3 * f + 1] = fmaf(v1, pre1, pre3 * hy);
        sm[3 * f + 2] = fmaf(v2, pre1, pre3 * hz);

        __syncthreads();   // messages staged

        if (fcut != 0.0f) {  // uniform across block
            float* ov = out_v + (size_t)dst * 384;
            atomicAdd(&out_s[(size_t)dst * 128 + f], pre2);
            atomicAdd(&ov[f],       sm[f]);
            atomicAdd(&ov[f + 128], sm[f + 128]);
            atomicAdd(&ov[f + 256], sm[f + 256]);
        }

        __syncthreads();   // protect sm before next staging
    }
}

// ---------------------------------------------------------------------------
// Launch
// Inputs (metadata order): node_scalar, node_vector, r_vec, W1, b1, W2, b2,
//                          Wr, br, edge_idx
// Output: [node_scalar' (N*128) | node_vector' (N*128*3)] float32
// ---------------------------------------------------------------------------
extern "C" void kernel_launch(void* const* d_in, const int* in_sizes, int n_in,
                              void* d_out, int out_size)
{
    const float* node_scalar = (const float*)d_in[0];
    const float* node_vector = (const float*)d_in[1];
    const float* r_vec       = (const float*)d_in[2];
    const float* W1          = (const float*)d_in[3];
    const float* b1          = (const float*)d_in[4];
    const float* W2          = (const float*)d_in[5];
    const float* b2          = (const float*)d_in[6];
    const float* Wr          = (const float*)d_in[7];
    const float* br          = (const float*)d_in[8];
    const int*   edge_idx    = (const int*)d_in[9];

    const int N = in_sizes[0] / F_DIM;          // 50000
    const int E = in_sizes[9] / 2;              // 800000

    float* out_s = (float*)d_out;
    float* out_v = out_s + (size_t)N * F_DIM;

    // Initialize output with node_scalar / node_vector (atomics add deltas)
    cudaMemcpyAsync(out_s, node_scalar, (size_t)N * 128 * sizeof(float),
                    cudaMemcpyDeviceToDevice, 0);
    cudaMemcpyAsync(out_v, node_vector, (size_t)N * 384 * sizeof(float),
                    cudaMemcpyDeviceToDevice, 0);

    float* d_h;   cudaGetSymbolAddress((void**)&d_h,   g_h);
    float* d_phi; cudaGetSymbolAddress((void**)&d_phi, g_phi);

    // Per-node: H = silu(X @ W1 + b1)  (padded rows -> silu(b1), deterministic)
    dim3 g1((N_PAD + 127) / 128, 1);
    gemm_bias_act<<<g1, 256>>>(node_scalar, W1, b1, d_h, N, 128, 1);

    // Per-node: PHI = H @ W2 + b2
    dim3 g2((N_PAD + 127) / 128, 3);
    gemm_bias_act<<<g2, 256>>>(d_h, W2, b2, d_phi, N_PAD, 384, 0);

    // Per-edge fused rbf + modulation + scatter
    edge_kernel<<<1184, 128>>>(r_vec, (const int2*)edge_idx, node_vector,
                               Wr, br, out_s, out_v, E);
}

// round 3
// speedup vs baseline: 1.4235x; 1.4235x over previous
#include <cuda_runtime.h>
#include <math.h>

#define F_DIM   128
#define NRBF    20
#define CUTOFF  5.0f
#define N_PAD   50048   // 391 * 128
#define PI_F    3.14159265358979323846f

// Scratch (allocation-free rule: __device__ globals)
__device__ float g_h[(size_t)N_PAD * 128];
__device__ float g_phi[(size_t)N_PAD * 384];

// ---------------------------------------------------------------------------
// GEMM: C[M x N] = act(A[M x 128] @ W[128 x N] + bias), K fixed = 128.
// BM=BN=128, BK=32, 256 threads, 8x8 micro-tile.
// ---------------------------------------------------------------------------
__global__ __launch_bounds__(256) void gemm_bias_act(
    const float* __restrict__ A, const float* __restrict__ W,
    const float* __restrict__ bias, float* __restrict__ C,
    int Mload, int N, int applySilu)
{
    __shared__ float As[128][33];   // [m][k], padded
    __shared__ float Ws[32][128];   // [k][n]

    const int tid = threadIdx.x;
    const int tx = tid % 16;        // col group
    const int ty = tid / 16;        // row group
    const int row0 = blockIdx.x * 128;
    const int col0 = blockIdx.y * 128;

    float acc[8][8];
#pragma unroll
    for (int i = 0; i < 8; i++)
#pragma unroll
        for (int j = 0; j < 8; j++) acc[i][j] = 0.0f;

    for (int k0 = 0; k0 < 128; k0 += 32) {
#pragma unroll
        for (int it = 0; it < 4; it++) {
            int r  = (tid / 8) + it * 32;
            int kq = (tid % 8) * 4;
            float4 v = make_float4(0.f, 0.f, 0.f, 0.f);
            int grow = row0 + r;
            if (grow < Mload)
                v = *(const float4*)(A + (size_t)grow * 128 + k0 + kq);
            As[r][kq + 0] = v.x; As[r][kq + 1] = v.y;
            As[r][kq + 2] = v.z; As[r][kq + 3] = v.w;
        }
        {
            const float* wbase = W + (size_t)k0 * N + col0;
#pragma unroll
            for (int it = 0; it < 4; it++) {
                int kr = (tid / 32) + it * 8;
                int cq = (tid % 32) * 4;
                float4 v = *(const float4*)(wbase + (size_t)kr * N + cq);
                *(float4*)&Ws[kr][cq] = v;
            }
        }
        __syncthreads();

#pragma unroll
        for (int k = 0; k < 32; k++) {
            float a[8], w[8];
#pragma unroll
            for (int i = 0; i < 8; i++) a[i] = As[ty * 8 + i][k];
            float4 w0 = *(float4*)&Ws[k][tx * 8];
            float4 w1 = *(float4*)&Ws[k][tx * 8 + 4];
            w[0] = w0.x; w[1] = w0.y; w[2] = w0.z; w[3] = w0.w;
            w[4] = w1.x; w[5] = w1.y; w[6] = w1.z; w[7] = w1.w;
#pragma unroll
            for (int i = 0; i < 8; i++)
#pragma unroll
                for (int j = 0; j < 8; j++)
                    acc[i][j] = fmaf(a[i], w[j], acc[i][j]);
        }
        __syncthreads();
    }

    float bcol[8];
#pragma unroll
    for (int j = 0; j < 8; j++) bcol[j] = bias[col0 + tx * 8 + j];

#pragma unroll
    for (int i = 0; i < 8; i++) {
        int grow = row0 + ty * 8 + i;
        float out[8];
#pragma unroll
        for (int j = 0; j < 8; j++) {
            float x = acc[i][j] + bcol[j];
            if (applySilu) x = x / (1.0f + __expf(-x));
            out[j] = x;
        }
        float* cp = C + (size_t)grow * N + col0 + tx * 8;
        *(float4*)cp       = make_float4(out[0], out[1], out[2], out[3]);
        *(float4*)(cp + 4) = make_float4(out[4], out[5], out[6], out[7]);
    }
}

// ---------------------------------------------------------------------------
// Edge kernel, sync-free, 2-edge ILP. 128 threads/block; thread f owns
// channels f, 128+f, 256+f. Wr columns register-resident (persistent loop).
// node_vector read / messages scattered directly (stride-3 warp accesses
// cover every sector of the 1536B row exactly once after L1 — no waste).
// No shared memory, no __syncthreads.
// ---------------------------------------------------------------------------
__global__ __launch_bounds__(128, 4) void edge_kernel(
    const float* __restrict__ r_vec,
    const int2*  __restrict__ edge_idx,
    const float* __restrict__ node_vector,
    const float* __restrict__ Wr,
    const float* __restrict__ br,
    float* __restrict__ out_s,   // [N,128], pre-initialized with node_scalar
    float* __restrict__ out_v,   // [N,128,3], pre-initialized with node_vector
    int E)
{
    const int f = threadIdx.x;

    float wr1[NRBF], wr2[NRBF], wr3[NRBF];
#pragma unroll
    for (int n = 0; n < NRBF; n++) {
        wr1[n] = Wr[n * 384 + f];
        wr2[n] = Wr[n * 384 + 128 + f];
        wr3[n] = Wr[n * 384 + 256 + f];
    }
    const float bias1 = br[f], bias2 = br[128 + f], bias3 = br[256 + f];

    const int stride = gridDim.x * 2;
    for (int e = blockIdx.x * 2; e < E; e += stride) {
        const bool hasB = (e + 1 < E);

        // --- issue all independent loads up front (MLP) ---
        const int2 eiA = __ldg(&edge_idx[e]);
        const int2 eiB = hasB ? __ldg(&edge_idx[e + 1]) : eiA;

        const float rxA = __ldg(&r_vec[3 * e]);
        const float ryA = __ldg(&r_vec[3 * e + 1]);
        const float rzA = __ldg(&r_vec[3 * e + 2]);
        const float rxB = hasB ? __ldg(&r_vec[3 * e + 3]) : 1.0f;
        const float ryB = hasB ? __ldg(&r_vec[3 * e + 4]) : 0.0f;
        const float rzB = hasB ? __ldg(&r_vec[3 * e + 5]) : 0.0f;

        const float* phA = g_phi + (size_t)eiA.y * 384;
        const float* phB = g_phi + (size_t)eiB.y * 384;
        const float p1A = phA[f], p2A = phA[f + 128], p3A = phA[f + 256];
        const float p1B = phB[f], p2B = phB[f + 128], p3B = phB[f + 256];

        const float* nvA = node_vector + (size_t)eiA.y * 384 + 3 * f;
        const float* nvB = node_vector + (size_t)eiB.y * 384 + 3 * f;
        const float v0A = nvA[0], v1A = nvA[1], v2A = nvA[2];
        const float v0B = nvB[0], v1B = nvB[1], v2B = nvB[2];

        // --- geometry ---
        const float dA = sqrtf(rxA * rxA + ryA * ryA + rzA * rzA);
        const float dB = sqrtf(rxB * rxB + ryB * ryB + rzB * rzB);
        const float invdA = 1.0f / dA, invdB = 1.0f / dB;
        float sA, cA, sB, cB;
        __sincosf(dA * (PI_F / CUTOFF), &sA, &cA);
        __sincosf(dB * (PI_F / CUTOFF), &sB, &cB);
        const float fcutA = (dA < CUTOFF) ? 0.5f * (cA + 1.0f) : 0.0f;
        const float fcutB = (dB < CUTOFF) ? 0.5f * (cB + 1.0f) : 0.0f;

        // --- rbf = sinc @ Wr + br via Chebyshev recurrence, fused A+B ---
        float a1A = bias1, a2A = bias2, a3A = bias3;
        float a1B = bias1, a2B = bias2, a3B = bias3;
        float spA = 0.0f, scA = sA, spB = 0.0f, scB = sB;
        const float twoCA = 2.0f * cA, twoCB = 2.0f * cB;
#pragma unroll
        for (int n = 0; n < NRBF; n++) {
            const float sncA = scA * invdA;
            const float sncB = scB * invdB;
            a1A = fmaf(sncA, wr1[n], a1A);
            a2A = fmaf(sncA, wr2[n], a2A);
            a3A = fmaf(sncA, wr3[n], a3A);
            a1B = fmaf(sncB, wr1[n], a1B);
            a2B = fmaf(sncB, wr2[n], a2B);
            a3B = fmaf(sncB, wr3[n], a3B);
            const float nxA = fmaf(twoCA, scA, -spA);
            const float nxB = fmaf(twoCB, scB, -spB);
            spA = scA; scA = nxA;
            spB = scB; scB = nxB;
        }

        // --- edge A scatter ---
        {
            const float pre1 = p1A * a1A * fcutA;
            const float pre2 = p2A * a2A * fcutA;
            const float pre3 = p3A * a3A * fcutA;
            if (fcutA != 0.0f) {   // warp-uniform
                const float hx = rxA * invdA, hy = ryA * invdA, hz = rzA * invdA;
                float* ov = out_v + (size_t)eiA.x * 384 + 3 * f;
                atomicAdd(&out_s[(size_t)eiA.x * 128 + f], pre2);
                atomicAdd(&ov[0], fmaf(v0A, pre1, pre3 * hx));
                atomicAdd(&ov[1], fmaf(v1A, pre1, pre3 * hy));
                atomicAdd(&ov[2], fmaf(v2A, pre1, pre3 * hz));
            }
        }
        // --- edge B scatter ---
        if (hasB && fcutB != 0.0f) {
            const float pre1 = p1B * a1B * fcutB;
            const float pre2 = p2B * a2B * fcutB;
            const float pre3 = p3B * a3B * fcutB;
            const float hx = rxB * invdB, hy = ryB * invdB, hz = rzB * invdB;
            float* ov = out_v + (size_t)eiB.x * 384 + 3 * f;
            atomicAdd(&out_s[(size_t)eiB.x * 128 + f], pre2);
            atomicAdd(&ov[0], fmaf(v0B, pre1, pre3 * hx));
            atomicAdd(&ov[1], fmaf(v1B, pre1, pre3 * hy));
            atomicAdd(&ov[2], fmaf(v2B, pre1, pre3 * hz));
        }
    }
}

// ---------------------------------------------------------------------------
// Launch
// ---------------------------------------------------------------------------
extern "C" void kernel_launch(void* const* d_in, const int* in_sizes, int n_in,
                              void* d_out, int out_size)
{
    const float* node_scalar = (const float*)d_in[0];
    const float* node_vector = (const float*)d_in[1];
    const float* r_vec       = (const float*)d_in[2];
    const float* W1          = (const float*)d_in[3];
    const float* b1          = (const float*)d_in[4];
    const float* W2          = (const float*)d_in[5];
    const float* b2          = (const float*)d_in[6];
    const float* Wr          = (const float*)d_in[7];
    const float* br          = (const float*)d_in[8];
    const int*   edge_idx    = (const int*)d_in[9];

    const int N = in_sizes[0] / F_DIM;          // 50000
    const int E = in_sizes[9] / 2;              // 800000

    float* out_s = (float*)d_out;
    float* out_v = out_s + (size_t)N * F_DIM;

    cudaMemcpyAsync(out_s, node_scalar, (size_t)N * 128 * sizeof(float),
                    cudaMemcpyDeviceToDevice, 0);
    cudaMemcpyAsync(out_v, node_vector, (size_t)N * 384 * sizeof(float),
                    cudaMemcpyDeviceToDevice, 0);

    float* d_h;   cudaGetSymbolAddress((void**)&d_h,   g_h);
    float* d_phi; cudaGetSymbolAddress((void**)&d_phi, g_phi);

    dim3 g1((N_PAD + 127) / 128, 1);
    gemm_bias_act<<<g1, 256>>>(node_scalar, W1, b1, d_h, N, 128, 1);

    dim3 g2((N_PAD + 127) / 128, 3);
    gemm_bias_act<<<g2, 256>>>(d_h, W2, b2, d_phi, N_PAD, 384, 0);

    // Persistent, sync-free edge kernel: 148 SMs x 4 resident blocks
    edge_kernel<<<592, 128>>>(r_vec, (const int2*)edge_idx, node_vector,
                              Wr, br, out_s, out_v, E);
}

// round 4
// speedup vs baseline: 1.4518x; 1.0199x over previous
#include <cuda_runtime.h>
#include <math.h>

#define F_DIM   128
#define NRBF    20
#define CUTOFF  5.0f
#define N_PAD   50048   // 391 * 128
#define E_MAX   800000
#define PI_F    3.14159265358979323846f

// Scratch (allocation-free rule: __device__ globals)
__device__ float  g_h[(size_t)N_PAD * 128];
__device__ float  g_phi[(size_t)N_PAD * 384];
__device__ int    g_hist[N_PAD];           // histogram -> excl offsets -> cursor
__device__ int    g_srcA[E_MAX];           // dst-sorted src
__device__ int    g_dstA[E_MAX];           // dst-sorted dst
__device__ float4 g_rvA[E_MAX];            // dst-sorted r_vec (xyz, pad)

// ---------------------------------------------------------------------------
// GEMM: C[M x N] = act(A[M x 128] @ W[128 x N] + bias), K fixed = 128.
// ---------------------------------------------------------------------------
__global__ __launch_bounds__(256) void gemm_bias_act(
    const float* __restrict__ A, const float* __restrict__ W,
    const float* __restrict__ bias, float* __restrict__ C,
    int Mload, int N, int applySilu)
{
    __shared__ float As[128][33];
    __shared__ float Ws[32][128];

    const int tid = threadIdx.x;
    const int tx = tid % 16;
    const int ty = tid / 16;
    const int row0 = blockIdx.x * 128;
    const int col0 = blockIdx.y * 128;

    float acc[8][8];
#pragma unroll
    for (int i = 0; i < 8; i++)
#pragma unroll
        for (int j = 0; j < 8; j++) acc[i][j] = 0.0f;

    for (int k0 = 0; k0 < 128; k0 += 32) {
#pragma unroll
        for (int it = 0; it < 4; it++) {
            int r  = (tid / 8) + it * 32;
            int kq = (tid % 8) * 4;
            float4 v = make_float4(0.f, 0.f, 0.f, 0.f);
            int grow = row0 + r;
            if (grow < Mload)
                v = *(const float4*)(A + (size_t)grow * 128 + k0 + kq);
            As[r][kq + 0] = v.x; As[r][kq + 1] = v.y;
            As[r][kq + 2] = v.z; As[r][kq + 3] = v.w;
        }
        {
            const float* wbase = W + (size_t)k0 * N + col0;
#pragma unroll
            for (int it = 0; it < 4; it++) {
                int kr = (tid / 32) + it * 8;
                int cq = (tid % 32) * 4;
                float4 v = *(const float4*)(wbase + (size_t)kr * N + cq);
                *(float4*)&Ws[kr][cq] = v;
            }
        }
        __syncthreads();

#pragma unroll
        for (int k = 0; k < 32; k++) {
            float a[8], w[8];
#pragma unroll
            for (int i = 0; i < 8; i++) a[i] = As[ty * 8 + i][k];
            float4 w0 = *(float4*)&Ws[k][tx * 8];
            float4 w1 = *(float4*)&Ws[k][tx * 8 + 4];
            w[0] = w0.x; w[1] = w0.y; w[2] = w0.z; w[3] = w0.w;
            w[4] = w1.x; w[5] = w1.y; w[6] = w1.z; w[7] = w1.w;
#pragma unroll
            for (int i = 0; i < 8; i++)
#pragma unroll
                for (int j = 0; j < 8; j++)
                    acc[i][j] = fmaf(a[i], w[j], acc[i][j]);
        }
        __syncthreads();
    }

    float bcol[8];
#pragma unroll
    for (int j = 0; j < 8; j++) bcol[j] = bias[col0 + tx * 8 + j];

#pragma unroll
    for (int i = 0; i < 8; i++) {
        int grow = row0 + ty * 8 + i;
        float out[8];
#pragma unroll
        for (int j = 0; j < 8; j++) {
            float x = acc[i][j] + bcol[j];
            if (applySilu) x = x / (1.0f + __expf(-x));
            out[j] = x;
        }
        float* cp = C + (size_t)grow * N + col0 + tx * 8;
        *(float4*)cp       = make_float4(out[0], out[1], out[2], out[3]);
        *(float4*)(cp + 4) = make_float4(out[4], out[5], out[6], out[7]);
    }
}

// ---------------------------------------------------------------------------
// Counting sort by dst: histogram -> exclusive scan -> scatter
// ---------------------------------------------------------------------------
__global__ void hist_kernel(const int2* __restrict__ edge_idx,
                            int* __restrict__ hist, int E)
{
    int e = blockIdx.x * blockDim.x + threadIdx.x;
    if (e < E) atomicAdd(&hist[edge_idx[e].x], 1);
}

// Single-block exclusive scan, in place (counts -> offsets).
__global__ __launch_bounds__(1024) void scan_kernel(int* __restrict__ data, int n)
{
    __shared__ int wsum[32];
    __shared__ int carry_s;
    const int lane = threadIdx.x & 31, wid = threadIdx.x >> 5;
    if (threadIdx.x == 0) carry_s = 0;
    __syncthreads();
    for (int base = 0; base < n; base += 1024) {
        int i = base + threadIdx.x;
        int v = (i < n) ? data[i] : 0;
        int x = v;
#pragma unroll
        for (int d = 1; d < 32; d <<= 1) {
            int y = __shfl_up_sync(0xFFFFFFFFu, x, d);
            if (lane >= d) x += y;
        }
        if (lane == 31) wsum[wid] = x;
        __syncthreads();
        if (wid == 0) {
            int s = wsum[lane];
#pragma unroll
            for (int d = 1; d < 32; d <<= 1) {
                int y = __shfl_up_sync(0xFFFFFFFFu, s, d);
                if (lane >= d) s += y;
            }
            wsum[lane] = s;
        }
        __syncthreads();
        int incl = x + (wid > 0 ? wsum[wid - 1] : 0) + carry_s;
        if (i < n) data[i] = incl - v;
        __syncthreads();                  // all reads of carry_s done
        if (threadIdx.x == 1023) carry_s = incl;
        __syncthreads();
    }
}

__global__ void scatter_kernel(const int2* __restrict__ edge_idx,
                               const float* __restrict__ r_vec,
                               int* __restrict__ cursor,
                               int* __restrict__ srcA, int* __restrict__ dstA,
                               float4* __restrict__ rvA, int E)
{
    int e = blockIdx.x * blockDim.x + threadIdx.x;
    if (e >= E) return;
    int2 ei = edge_idx[e];
    int p = atomicAdd(&cursor[ei.x], 1);
    srcA[p] = ei.y;
    dstA[p] = ei.x;
    rvA[p]  = make_float4(r_vec[3 * e], r_vec[3 * e + 1], r_vec[3 * e + 2], 0.f);
}

// ---------------------------------------------------------------------------
// Edge kernel v3: dst-sorted chunks, register accumulation, one atomic flush
// per dst-run (~16x fewer atomics). Software-pipelined gathers (distance 1).
// 128 threads/block; thread f owns channels f, 128+f, 256+f (vec 3f..3f+2).
// ---------------------------------------------------------------------------
__global__ __launch_bounds__(128, 4) void edge_kernel(
    const float4* __restrict__ rvA,
    const int*    __restrict__ srcA,
    const int*    __restrict__ dstA,
    const float*  __restrict__ node_vector,
    const float*  __restrict__ Wr,
    const float*  __restrict__ br,
    float* __restrict__ out_s,
    float* __restrict__ out_v,
    int E, int chunk)
{
    const int f = threadIdx.x;

    float wr1[NRBF], wr2[NRBF], wr3[NRBF];
#pragma unroll
    for (int n = 0; n < NRBF; n++) {
        wr1[n] = Wr[n * 384 + f];
        wr2[n] = Wr[n * 384 + 128 + f];
        wr3[n] = Wr[n * 384 + 256 + f];
    }
    const float bias1 = br[f], bias2 = br[128 + f], bias3 = br[256 + f];

    const int beg = blockIdx.x * chunk;
    const int end = min(E, beg + chunk);
    if (beg >= end) return;

    float accS = 0.f, acc0 = 0.f, acc1 = 0.f, acc2 = 0.f;

    // prologue: load edge beg
    int    src_c = srcA[beg];
    int    dst_c = dstA[beg];
    float4 rv_c  = rvA[beg];
    const float* ph = g_phi + (size_t)src_c * 384;
    float p1 = ph[f], p2 = ph[f + 128], p3 = ph[f + 256];
    const float* nv = node_vector + (size_t)src_c * 384 + 3 * f;
    float v0 = nv[0], v1 = nv[1], v2 = nv[2];

    int curDst = dst_c;

    for (int i = beg; i < end; i++) {
        // ---- prefetch edge i+1 ----
        int    src_n = 0, dst_n = -1;
        float4 rv_n  = make_float4(1.f, 0.f, 0.f, 0.f);
        float  p1n = 0.f, p2n = 0.f, p3n = 0.f, v0n = 0.f, v1n = 0.f, v2n = 0.f;
        if (i + 1 < end) {
            src_n = srcA[i + 1];
            dst_n = dstA[i + 1];
            rv_n  = rvA[i + 1];
            const float* phn = g_phi + (size_t)src_n * 384;
            p1n = phn[f]; p2n = phn[f + 128]; p3n = phn[f + 256];
            const float* nvn = node_vector + (size_t)src_n * 384 + 3 * f;
            v0n = nvn[0]; v1n = nvn[1]; v2n = nvn[2];
        }

        // ---- flush if dst changed ----
        if (dst_c != curDst) {
            atomicAdd(&out_s[(size_t)curDst * 128 + f], accS);
            float* ov = out_v + (size_t)curDst * 384 + 3 * f;
            atomicAdd(&ov[0], acc0);
            atomicAdd(&ov[1], acc1);
            atomicAdd(&ov[2], acc2);
            accS = acc0 = acc1 = acc2 = 0.f;
            curDst = dst_c;
        }

        // ---- compute edge i ----
        const float rx = rv_c.x, ry = rv_c.y, rz = rv_c.z;
        const float d    = sqrtf(rx * rx + ry * ry + rz * rz);
        const float invd = 1.0f / d;
        float s, c;
        __sincosf(d * (PI_F / CUTOFF), &s, &c);
        const float fcut = (d < CUTOFF) ? 0.5f * (c + 1.0f) : 0.0f;

        float a1 = bias1, a2 = bias2, a3 = bias3;
        float sp = 0.0f, sc = s;
        const float twoC = 2.0f * c;
#pragma unroll
        for (int n = 0; n < NRBF; n++) {
            const float snc = sc * invd;
            a1 = fmaf(snc, wr1[n], a1);
            a2 = fmaf(snc, wr2[n], a2);
            a3 = fmaf(snc, wr3[n], a3);
            const float nx = fmaf(twoC, sc, -sp);
            sp = sc; sc = nx;
        }

        if (fcut != 0.0f) {    // warp-uniform
            const float pre1 = p1 * a1 * fcut;
            const float pre2 = p2 * a2 * fcut;
            const float pre3 = p3 * a3 * fcut;
            const float hx = rx * invd, hy = ry * invd, hz = rz * invd;
            accS += pre2;
            acc0 = fmaf(v0, pre1, fmaf(pre3, hx, acc0));
            acc1 = fmaf(v1, pre1, fmaf(pre3, hy, acc1));
            acc2 = fmaf(v2, pre1, fmaf(pre3, hz, acc2));
        }

        // ---- rotate pipeline ----
        src_c = src_n; dst_c = dst_n; rv_c = rv_n;
        p1 = p1n; p2 = p2n; p3 = p3n;
        v0 = v0n; v1 = v1n; v2 = v2n;
    }

    // final flush
    atomicAdd(&out_s[(size_t)curDst * 128 + f], accS);
    float* ov = out_v + (size_t)curDst * 384 + 3 * f;
    atomicAdd(&ov[0], acc0);
    atomicAdd(&ov[1], acc1);
    atomicAdd(&ov[2], acc2);
}

// ---------------------------------------------------------------------------
// Launch
// ---------------------------------------------------------------------------
extern "C" void kernel_launch(void* const* d_in, const int* in_sizes, int n_in,
                              void* d_out, int out_size)
{
    const float* node_scalar = (const float*)d_in[0];
    const float* node_vector = (const float*)d_in[1];
    const float* r_vec       = (const float*)d_in[2];
    const float* W1          = (const float*)d_in[3];
    const float* b1          = (const float*)d_in[4];
    const float* W2          = (const float*)d_in[5];
    const float* b2          = (const float*)d_in[6];
    const float* Wr          = (const float*)d_in[7];
    const float* br          = (const float*)d_in[8];
    const int*   edge_idx    = (const int*)d_in[9];

    const int N = in_sizes[0] / F_DIM;          // 50000
    const int E = in_sizes[9] / 2;              // 800000

    float* out_s = (float*)d_out;
    float* out_v = out_s + (size_t)N * F_DIM;

    cudaMemcpyAsync(out_s, node_scalar, (size_t)N * 128 * sizeof(float),
                    cudaMemcpyDeviceToDevice, 0);
    cudaMemcpyAsync(out_v, node_vector, (size_t)N * 384 * sizeof(float),
                    cudaMemcpyDeviceToDevice, 0);

    float*  d_h;    cudaGetSymbolAddress((void**)&d_h,    g_h);
    float*  d_phi;  cudaGetSymbolAddress((void**)&d_phi,  g_phi);
    int*    d_hist; cudaGetSymbolAddress((void**)&d_hist, g_hist);
    int*    d_srcA; cudaGetSymbolAddress((void**)&d_srcA, g_srcA);
    int*    d_dstA; cudaGetSymbolAddress((void**)&d_dstA, g_dstA);
    float4* d_rvA;  cudaGetSymbolAddress((void**)&d_rvA,  g_rvA);

    // --- counting sort by dst ---
    cudaMemsetAsync(d_hist, 0, (size_t)N * sizeof(int), 0);
    hist_kernel<<<(E + 255) / 256, 256>>>((const int2*)edge_idx, d_hist, E);
    scan_kernel<<<1, 1024>>>(d_hist, N);
    scatter_kernel<<<(E + 255) / 256, 256>>>((const int2*)edge_idx, r_vec,
                                             d_hist, d_srcA, d_dstA, d_rvA, E);

    // --- per-node GEMMs ---
    dim3 g1((N_PAD + 127) / 128, 1);
    gemm_bias_act<<<g1, 256>>>(node_scalar, W1, b1, d_h, N, 128, 1);
    dim3 g2((N_PAD + 127) / 128, 3);
    gemm_bias_act<<<g2, 256>>>(d_h, W2, b2, d_phi, N_PAD, 384, 0);

    // --- dst-sorted edge kernel ---
    const int grid  = 592;                      // 148 SMs x 4 blocks
    const int chunk = (E + grid - 1) / grid;
    edge_kernel<<<grid, 128>>>(d_rvA, d_srcA, d_dstA, node_vector,
                               Wr, br, out_s, out_v, E, chunk);
}